// round 5
// baseline (speedup 1.0000x reference)
#include <cuda_runtime.h>
#include <math.h>

#define Bb 4
#define Ss 1024
#define Dd 512
#define Hh 8
#define DKk 64
#define Mrows 4096   // B*S
#define SST 1028     // Ssm row stride (bank-conflict pad)

// ---------------- scratch (no allocations allowed) ----------------
__device__ float g_qp[Mrows * Dd];
__device__ float g_kp[Mrows * Dd];
__device__ float g_vp[Mrows * Dd];
__device__ float g_op[Mrows * Dd];
__device__ float g_freq[32];

// ---------------- RoPE frequency table ----------------
__global__ void freq_init_kernel() {
    int t = threadIdx.x;
    if (t < 32) {
        g_freq[t] = (float)exp(-((double)(2 * t) / 64.0) * log(10000.0));
    }
}

// ---------------- tf32 helpers ----------------
__device__ __forceinline__ unsigned f2tf32(float a) {
    unsigned r;
    asm("cvt.rna.tf32.f32 %0, %1;" : "=r"(r) : "f"(a));
    return r;
}
__device__ __forceinline__ void split1(float f, unsigned& h, unsigned& l) {
    h = f2tf32(f);
    l = f2tf32(f - __uint_as_float(h));
}

__device__ __forceinline__ void mma_tf32(
    float& c0, float& c1, float& c2, float& c3,
    unsigned a0, unsigned a1, unsigned a2, unsigned a3,
    unsigned b0, unsigned b1) {
    asm volatile(
        "mma.sync.aligned.m16n8k8.row.col.f32.tf32.tf32.f32 "
        "{%0,%1,%2,%3}, {%4,%5,%6,%7}, {%8,%9}, {%0,%1,%2,%3};"
        : "+f"(c0), "+f"(c1), "+f"(c2), "+f"(c3)
        : "r"(a0), "r"(a1), "r"(a2), "r"(a3), "r"(b0), "r"(b1));
}

// ---------------- shared GEMM core: 64x64 tile, 128 thr, 3xTF32 ----------------
__device__ __forceinline__ void gemm_core(
    const float* __restrict__ A, const float* __restrict__ W,
    const float* __restrict__ bias, float* __restrict__ C,
    int rope, int rowBase, int colBase) {
    __shared__ __align__(16) unsigned AsH[64 * 20], AsL[64 * 20];
    __shared__ __align__(16) unsigned BsH[64 * 20], BsL[64 * 20];
    const int tid = threadIdx.x;
    const int warp = tid >> 5, lane = tid & 31;
    const int g = lane >> 2, t4 = lane & 3;
    const int wm = (warp >> 1) << 5;
    const int wn = (warp & 1) << 5;

    float acc[2][4][4];
#pragma unroll
    for (int i = 0; i < 2; i++)
#pragma unroll
        for (int j = 0; j < 4; j++)
#pragma unroll
            for (int kq = 0; kq < 4; kq++) acc[i][j][kq] = 0.0f;

    float4 pa[2], pb[2];
#pragma unroll
    for (int l = 0; l < 2; l++) {
        int e = tid + (l << 7);
        int r = e >> 2, kq = (e & 3) << 2;
        pa[l] = *(const float4*)&A[(size_t)(rowBase + r) * 512 + kq];
        pb[l] = *(const float4*)&W[(size_t)(colBase + r) * 512 + kq];
    }

    for (int kt = 0; kt < 512; kt += 16) {
#pragma unroll
        for (int l = 0; l < 2; l++) {
            int e = tid + (l << 7);
            int r = e >> 2, kq = (e & 3) << 2;
            float av[4] = {pa[l].x, pa[l].y, pa[l].z, pa[l].w};
            float bv[4] = {pb[l].x, pb[l].y, pb[l].z, pb[l].w};
#pragma unroll
            for (int u = 0; u < 4; u++) {
                split1(av[u], AsH[r * 20 + kq + u], AsL[r * 20 + kq + u]);
                split1(bv[u], BsH[r * 20 + kq + u], BsL[r * 20 + kq + u]);
            }
        }
        __syncthreads();
        if (kt + 16 < 512) {
#pragma unroll
            for (int l = 0; l < 2; l++) {
                int e = tid + (l << 7);
                int r = e >> 2, kq = (e & 3) << 2;
                pa[l] = *(const float4*)&A[(size_t)(rowBase + r) * 512 + kt + 16 + kq];
                pb[l] = *(const float4*)&W[(size_t)(colBase + r) * 512 + kt + 16 + kq];
            }
        }
#pragma unroll
        for (int ks = 0; ks < 16; ks += 8) {
            unsigned ah[2][4], al[2][4];
#pragma unroll
            for (int mt = 0; mt < 2; mt++) {
                int r0 = wm + (mt << 4) + g;
                ah[mt][0] = AsH[r0 * 20 + ks + t4];
                ah[mt][1] = AsH[(r0 + 8) * 20 + ks + t4];
                ah[mt][2] = AsH[r0 * 20 + ks + t4 + 4];
                ah[mt][3] = AsH[(r0 + 8) * 20 + ks + t4 + 4];
                al[mt][0] = AsL[r0 * 20 + ks + t4];
                al[mt][1] = AsL[(r0 + 8) * 20 + ks + t4];
                al[mt][2] = AsL[r0 * 20 + ks + t4 + 4];
                al[mt][3] = AsL[(r0 + 8) * 20 + ks + t4 + 4];
            }
#pragma unroll
            for (int nt = 0; nt < 4; nt++) {
                int n0 = wn + (nt << 3) + g;
                unsigned bh0 = BsH[n0 * 20 + ks + t4];
                unsigned bh1 = BsH[n0 * 20 + ks + t4 + 4];
                unsigned bl0 = BsL[n0 * 20 + ks + t4];
                unsigned bl1 = BsL[n0 * 20 + ks + t4 + 4];
#pragma unroll
                for (int mt = 0; mt < 2; mt++) {
                    float* c = acc[mt][nt];
                    mma_tf32(c[0], c[1], c[2], c[3],
                             ah[mt][0], ah[mt][1], ah[mt][2], ah[mt][3], bl0, bl1);
                    mma_tf32(c[0], c[1], c[2], c[3],
                             al[mt][0], al[mt][1], al[mt][2], al[mt][3], bh0, bh1);
                    mma_tf32(c[0], c[1], c[2], c[3],
                             ah[mt][0], ah[mt][1], ah[mt][2], ah[mt][3], bh0, bh1);
                }
            }
        }
        __syncthreads();
    }

#pragma unroll
    for (int nt = 0; nt < 4; nt++) {
        int col = colBase + wn + (nt << 3) + (t4 << 1);
        float bx = bias[col], by = bias[col + 1];
        int p = (col & 63) >> 1;
        float fr = g_freq[p];
#pragma unroll
        for (int mt = 0; mt < 2; mt++) {
            int row = rowBase + wm + (mt << 4) + g;
            float* c = acc[mt][nt];
            float x0 = c[0] + bx, x1 = c[1] + by;
            float y0 = c[2] + bx, y1 = c[3] + by;
            if (rope) {
                float sv, cv;
                sincosf((float)(row & 1023) * fr, &sv, &cv);
                float t0 = x0 * cv - x1 * sv;
                x1 = x1 * cv + x0 * sv; x0 = t0;
                sincosf((float)((row + 8) & 1023) * fr, &sv, &cv);
                float u0 = y0 * cv - y1 * sv;
                y1 = y1 * cv + y0 * sv; y0 = u0;
            }
            *(float2*)&C[(size_t)row * 512 + col] = make_float2(x0, x1);
            *(float2*)&C[(size_t)(row + 8) * 512 + col] = make_float2(y0, y1);
        }
    }
}

// merged projection GEMMs: z=0 q(+rope), z=1 k(+rope), z=2 v
__global__ __launch_bounds__(128) void proj_gemm_kernel(
    const float* __restrict__ q, const float* __restrict__ k,
    const float* __restrict__ v,
    const float* __restrict__ Wq, const float* __restrict__ bq,
    const float* __restrict__ Wv, const float* __restrict__ bv,
    float* __restrict__ qp, float* __restrict__ kp, float* __restrict__ vp) {
    const int z = blockIdx.z;
    const float* A = (z == 0) ? q : (z == 1) ? k : v;
    const float* W = (z == 2) ? Wv : Wq;
    const float* bias = (z == 2) ? bv : bq;
    float* C = (z == 0) ? qp : (z == 1) ? kp : vp;
    gemm_core(A, W, bias, C, z < 2, blockIdx.y << 6, blockIdx.x << 6);
}

__global__ __launch_bounds__(128) void gemm_bias_kernel(
    const float* __restrict__ A, const float* __restrict__ W,
    const float* __restrict__ bias, float* __restrict__ C) {
    gemm_core(A, W, bias, C, 0, blockIdx.y << 6, blockIdx.x << 6);
}

// ---------------- fused attention ----------------
// block = 16 query rows of one (b,h). 512 threads (16 warps), 1 CTA/SM.
// smem: Ssm[16][1028] scores/attn, QH/QL[16][68], KV[128][68], Psm[16][1024].
__global__ __launch_bounds__(512, 1) void attn_kernel(
    const float* __restrict__ qp, const float* __restrict__ kp,
    const float* __restrict__ vp, const float* __restrict__ gammas,
    float* __restrict__ attn_out, float* __restrict__ op) {
    extern __shared__ __align__(16) float sm[];
    float* Ssm = sm;                                   // 16*1028
    unsigned* QH = (unsigned*)(sm + 16 * SST);         // 16*68
    unsigned* QL = QH + 16 * 68;                       // 16*68
    float* KV = (float*)(QL + 16 * 68);                // 128*68
    float* Psm = KV + 128 * 68;                        // 16*1024

    const int tid = threadIdx.x;
    const int bh = blockIdx.y, b = bh >> 3, h = bh & 7;
    const int i0 = (int)(gridDim.x - 1 - blockIdx.x) << 4;  // big blocks first
    const int jtMax = (i0 + 15) >> 7;
    const int warp = tid >> 5, lane = tid & 31;
    const int g = lane >> 2, t4 = lane & 3;

    // load+scale+split Q tile (threads 0..255: one float4 each)
    if (tid < 256) {
        int r = tid >> 4, dq = (tid & 15) << 2;
        float4 v = *(const float4*)&qp[(size_t)((b << 10) + i0 + r) * 512 + (h << 6) + dq];
        split1(v.x * 0.125f, QH[r * 68 + dq + 0], QL[r * 68 + dq + 0]);
        split1(v.y * 0.125f, QH[r * 68 + dq + 1], QL[r * 68 + dq + 1]);
        split1(v.z * 0.125f, QH[r * 68 + dq + 2], QL[r * 68 + dq + 2]);
        split1(v.w * 0.125f, QH[r * 68 + dq + 3], QL[r * 68 + dq + 3]);
    }
    __syncthreads();

    // ---- scores = Q K^T via 3xTF32 mma; 128-wide j tiles, warp owns 8 cols ----
    for (int jt = 0; jt <= jtMax; jt++) {
        int j0 = jt << 7;
#pragma unroll
        for (int l = 0; l < 4; l++) {
            int e = tid + (l << 9);
            int j = e >> 4, dq = (e & 15) << 2;
            *(float4*)&KV[j * 68 + dq] =
                *(const float4*)&kp[(size_t)((b << 10) + j0 + j) * 512 + (h << 6) + dq];
        }
        __syncthreads();
        const int jn = warp << 3;   // warp's 8-col slice within tile
        float c0 = 0, c1 = 0, c2 = 0, c3 = 0;
#pragma unroll
        for (int ks = 0; ks < 64; ks += 8) {
            unsigned ah0 = QH[g * 68 + ks + t4];
            unsigned ah1 = QH[(g + 8) * 68 + ks + t4];
            unsigned ah2 = QH[g * 68 + ks + t4 + 4];
            unsigned ah3 = QH[(g + 8) * 68 + ks + t4 + 4];
            unsigned al0 = QL[g * 68 + ks + t4];
            unsigned al1 = QL[(g + 8) * 68 + ks + t4];
            unsigned al2 = QL[g * 68 + ks + t4 + 4];
            unsigned al3 = QL[(g + 8) * 68 + ks + t4 + 4];
            int j = jn + g;
            float kb0 = KV[j * 68 + ks + t4];
            float kb1 = KV[j * 68 + ks + t4 + 4];
            unsigned bh0, bl0, bh1, bl1;
            split1(kb0, bh0, bl0);
            split1(kb1, bh1, bl1);
            mma_tf32(c0, c1, c2, c3, ah0, ah1, ah2, ah3, bl0, bl1);
            mma_tf32(c0, c1, c2, c3, al0, al1, al2, al3, bh0, bh1);
            mma_tf32(c0, c1, c2, c3, ah0, ah1, ah2, ah3, bh0, bh1);
        }
        {
            int jc = j0 + jn + (t4 << 1);
            *(float2*)&Ssm[g * SST + jc] = make_float2(c0, c1);
            *(float2*)&Ssm[(g + 8) * SST + jc] = make_float2(c2, c3);
        }
        __syncthreads();
    }

    // ---- row phase: one warp per row ----
    const float gamma = gammas[h];
    const float gg = -(fmaxf(gamma, 0.0f) + log1pf(expf(-fabsf(gamma))));  // -softplus
    const float g2 = gg * gg;
    const float slope = exp2f(-(float)(h + 1));
    const int jpad = (jtMax + 1) << 7;
    {
        int r = warp;
        int gi = i0 + r;
        int n = gi + 1;
        float* Srow = Ssm + r * SST;
        float* Prow = Psm + (r << 10);

        // max
        float mx = -3.0e38f;
        for (int j = lane; j < n; j += 32) mx = fmaxf(mx, Srow[j]);
#pragma unroll
        for (int o = 16; o; o >>= 1) mx = fmaxf(mx, __shfl_xor_sync(0xffffffffu, mx, o));
        // sum of exp, cache e in Prow
        float se = 0.0f;
        for (int j = lane; j < n; j += 32) {
            float e = __expf(Srow[j] - mx);
            Prow[j] = e;
            se += e;
        }
#pragma unroll
        for (int o = 16; o; o >>= 1) se += __shfl_xor_sync(0xffffffffu, se, o);
        float inv = 1.0f / se;
        // disttot = sum of rounded probabilities (reuse cached e)
        float dt = 0.0f;
        for (int j = lane; j < n; j += 32) dt += Prow[j] * inv;
#pragma unroll
        for (int o = 16; o; o >>= 1) dt += __shfl_xor_sync(0xffffffffu, dt, o);

        // cumsum scan + effect + alibi, track max2 (reuse cached e)
        float carry = 0.0f, mx2 = -3.0e38f;
        for (int jb = 0; jb < n; jb += 32) {
            int j = jb + lane;
            float v = (j < n) ? Prow[j] * inv : 0.0f;
            float x = v;
#pragma unroll
            for (int o = 1; o < 32; o <<= 1) {
                float y = __shfl_up_sync(0xffffffffu, x, o);
                if (lane >= o) x += y;
            }
            if (j < n) {
                float cum = x + carry;
                float suf = dt - cum;
                float pos = (float)(gi - j);
                float d2 = fmaxf(suf, 0.0f) * pos;
                float eff;
                if (g2 * d2 > 132.6f) {
                    eff = 1e-5f;
                } else {
                    eff = fmaxf(__expf(gg * sqrtf(d2)), 1e-5f);
                }
                float s2 = Srow[j] * eff + slope * (float)j;
                Srow[j] = s2;
                mx2 = fmaxf(mx2, s2);
            }
            carry += __shfl_sync(0xffffffffu, x, 31);
        }
#pragma unroll
        for (int o = 16; o; o >>= 1) mx2 = fmaxf(mx2, __shfl_xor_sync(0xffffffffu, mx2, o));

        // softmax2 sum (store exp in place)
        float se2 = 0.0f;
        for (int j = lane; j < n; j += 32) {
            float dlt = Srow[j] - mx2;
            float e2 = (dlt > -87.3f) ? __expf(dlt) : 0.0f;
            Srow[j] = e2;
            se2 += e2;
        }
#pragma unroll
        for (int o = 16; o; o >>= 1) se2 += __shfl_xor_sync(0xffffffffu, se2, o);
        float inv2 = 1.0f / se2;

        float* arow = attn_out + ((size_t)bh << 20) + ((size_t)gi << 10);
        for (int j = lane; j < 1024; j += 32) {
            float a = (j < n) ? Srow[j] * inv2 : 0.0f;
            arow[j] = a;
            if (j < jpad) Srow[j] = a;
        }
    }
    __syncthreads();

    // ---- out = attn @ V (SIMT fp32): thread handles rows r2, r2+8; col c ----
    const int r2 = tid >> 6, c = tid & 63;
    float o0 = 0, o1 = 0;
    for (int jt = 0; jt <= jtMax; jt++) {
        int j0 = jt << 7;
#pragma unroll
        for (int l = 0; l < 4; l++) {
            int e = tid + (l << 9);
            int j = e >> 4, dq = (e & 15) << 2;
            *(float4*)&KV[j * 68 + dq] =
                *(const float4*)&vp[(size_t)((b << 10) + j0 + j) * 512 + (h << 6) + dq];
        }
        __syncthreads();
#pragma unroll 8
        for (int jq = 0; jq < 128; jq += 4) {
            float4 s0 = *(const float4*)&Ssm[r2 * SST + j0 + jq];
            float4 s1 = *(const float4*)&Ssm[(r2 + 8) * SST + j0 + jq];
            float v0 = KV[(jq + 0) * 68 + c];
            float v1 = KV[(jq + 1) * 68 + c];
            float v2 = KV[(jq + 2) * 68 + c];
            float v3 = KV[(jq + 3) * 68 + c];
            o0 += s0.x * v0 + s0.y * v1 + s0.z * v2 + s0.w * v3;
            o1 += s1.x * v0 + s1.y * v1 + s1.z * v2 + s1.w * v3;
        }
        __syncthreads();
    }
    op[(size_t)((b << 10) + i0 + r2) * 512 + (h << 6) + c] = o0;
    op[(size_t)((b << 10) + i0 + r2 + 8) * 512 + (h << 6) + c] = o1;
}

// ---------------- launch ----------------
extern "C" void kernel_launch(void* const* d_in, const int* in_sizes, int n_in,
                              void* d_out, int out_size) {
    const float* q      = (const float*)d_in[0];
    const float* k      = (const float*)d_in[1];
    const float* v      = (const float*)d_in[2];
    // d_in[3] = mask (tril causal) — structure used implicitly
    const float* Wq     = (const float*)d_in[4];
    const float* bq     = (const float*)d_in[5];
    const float* Wv     = (const float*)d_in[6];
    const float* bv     = (const float*)d_in[7];
    const float* Wo     = (const float*)d_in[8];
    const float* bo     = (const float*)d_in[9];
    const float* gammas = (const float*)d_in[10];

    float* out  = (float*)d_out;                       // [B,S,D]
    float* attn = out + (size_t)Mrows * Dd;            // [B,H,S,S]

    float *qp, *kp, *vp, *op;
    cudaGetSymbolAddress((void**)&qp, g_qp);
    cudaGetSymbolAddress((void**)&kp, g_kp);
    cudaGetSymbolAddress((void**)&vp, g_vp);
    cudaGetSymbolAddress((void**)&op, g_op);

    const int ATTN_SMEM = (16 * SST + 16 * 68 * 2 + 128 * 68 + 16 * 1024) * 4; // 174848
    cudaFuncSetAttribute(attn_kernel, cudaFuncAttributeMaxDynamicSharedMemorySize,
                         ATTN_SMEM);

    freq_init_kernel<<<1, 32>>>();

    proj_gemm_kernel<<<dim3(8, 64, 3), 128>>>(q, k, v, Wq, bq, Wv, bv, qp, kp, vp);

    attn_kernel<<<dim3(64, 32), 512, ATTN_SMEM>>>(qp, kp, vp, gammas, attn, op);

    gemm_bias_kernel<<<dim3(8, 64), 128>>>(op, Wo, bo, out);
}

// round 8
// speedup vs baseline: 1.0049x; 1.0049x over previous
#include <cuda_runtime.h>
#include <math.h>

#define Bb 4
#define Ss 1024
#define Dd 512
#define Hh 8
#define DKk 64
#define Mrows 4096   // B*S
#define SST 1028     // Ssm row stride (bank-conflict pad)

// ---------------- scratch (no allocations allowed) ----------------
__device__ float g_qp[Mrows * Dd];
__device__ float g_kp[Mrows * Dd];
__device__ float g_vp[Mrows * Dd];
__device__ float g_op[Mrows * Dd];
__device__ float g_freq[32];

// ---------------- RoPE frequency table ----------------
__global__ void freq_init_kernel() {
    int t = threadIdx.x;
    if (t < 32) {
        g_freq[t] = (float)exp(-((double)(2 * t) / 64.0) * log(10000.0));
    }
}

// ---------------- tf32 helpers ----------------
__device__ __forceinline__ unsigned f2tf32(float a) {
    unsigned r;
    asm("cvt.rna.tf32.f32 %0, %1;" : "=r"(r) : "f"(a));
    return r;
}
__device__ __forceinline__ void split1(float f, unsigned& h, unsigned& l) {
    h = f2tf32(f);
    l = f2tf32(f - __uint_as_float(h));
}

__device__ __forceinline__ void mma_tf32(
    float& c0, float& c1, float& c2, float& c3,
    unsigned a0, unsigned a1, unsigned a2, unsigned a3,
    unsigned b0, unsigned b1) {
    asm volatile(
        "mma.sync.aligned.m16n8k8.row.col.f32.tf32.tf32.f32 "
        "{%0,%1,%2,%3}, {%4,%5,%6,%7}, {%8,%9}, {%0,%1,%2,%3};"
        : "+f"(c0), "+f"(c1), "+f"(c2), "+f"(c3)
        : "r"(a0), "r"(a1), "r"(a2), "r"(a3), "r"(b0), "r"(b1));
}

// ---------------- shared GEMM core: 32x64 tile, 128 thr, 3xTF32 ----------------
// 4 warps = 2m x 2n, warp tile 16x32 (one m16 row-group, 4 n8 col-groups), BK=16.
__device__ __forceinline__ void gemm_core(
    const float* __restrict__ A, const float* __restrict__ W,
    const float* __restrict__ bias, float* __restrict__ C,
    int rope, int rowBase, int colBase) {
    __shared__ __align__(16) unsigned AsH[32 * 20], AsL[32 * 20];
    __shared__ __align__(16) unsigned BsH[64 * 20], BsL[64 * 20];
    const int tid = threadIdx.x;
    const int warp = tid >> 5, lane = tid & 31;
    const int g = lane >> 2, t4 = lane & 3;
    const int wm = (warp >> 1) << 4;   // 0 or 16
    const int wn = (warp & 1) << 5;    // 0 or 32

    float acc[4][4];
#pragma unroll
    for (int j = 0; j < 4; j++)
#pragma unroll
        for (int kq = 0; kq < 4; kq++) acc[j][kq] = 0.0f;

    // prefetch first tiles: A 32x16 (1 float4/thr), B 64x16 (2 float4/thr)
    float4 pa, pb[2];
    {
        int r = tid >> 2, kq = (tid & 3) << 2;
        pa = *(const float4*)&A[(size_t)(rowBase + r) * 512 + kq];
    }
#pragma unroll
    for (int l = 0; l < 2; l++) {
        int e = tid + (l << 7);
        int r = e >> 2, kq = (e & 3) << 2;
        pb[l] = *(const float4*)&W[(size_t)(colBase + r) * 512 + kq];
    }

    for (int kt = 0; kt < 512; kt += 16) {
        {
            int r = tid >> 2, kq = (tid & 3) << 2;
            float av[4] = {pa.x, pa.y, pa.z, pa.w};
#pragma unroll
            for (int u = 0; u < 4; u++)
                split1(av[u], AsH[r * 20 + kq + u], AsL[r * 20 + kq + u]);
        }
#pragma unroll
        for (int l = 0; l < 2; l++) {
            int e = tid + (l << 7);
            int r = e >> 2, kq = (e & 3) << 2;
            float bv[4] = {pb[l].x, pb[l].y, pb[l].z, pb[l].w};
#pragma unroll
            for (int u = 0; u < 4; u++)
                split1(bv[u], BsH[r * 20 + kq + u], BsL[r * 20 + kq + u]);
        }
        __syncthreads();
        if (kt + 16 < 512) {
            {
                int r = tid >> 2, kq = (tid & 3) << 2;
                pa = *(const float4*)&A[(size_t)(rowBase + r) * 512 + kt + 16 + kq];
            }
#pragma unroll
            for (int l = 0; l < 2; l++) {
                int e = tid + (l << 7);
                int r = e >> 2, kq = (e & 3) << 2;
                pb[l] = *(const float4*)&W[(size_t)(colBase + r) * 512 + kt + 16 + kq];
            }
        }
#pragma unroll
        for (int ks = 0; ks < 16; ks += 8) {
            int r0 = wm + g;
            unsigned ah0 = AsH[r0 * 20 + ks + t4];
            unsigned ah1 = AsH[(r0 + 8) * 20 + ks + t4];
            unsigned ah2 = AsH[r0 * 20 + ks + t4 + 4];
            unsigned ah3 = AsH[(r0 + 8) * 20 + ks + t4 + 4];
            unsigned al0 = AsL[r0 * 20 + ks + t4];
            unsigned al1 = AsL[(r0 + 8) * 20 + ks + t4];
            unsigned al2 = AsL[r0 * 20 + ks + t4 + 4];
            unsigned al3 = AsL[(r0 + 8) * 20 + ks + t4 + 4];
#pragma unroll
            for (int nt = 0; nt < 4; nt++) {
                int n0 = wn + (nt << 3) + g;
                unsigned bh0 = BsH[n0 * 20 + ks + t4];
                unsigned bh1 = BsH[n0 * 20 + ks + t4 + 4];
                unsigned bl0 = BsL[n0 * 20 + ks + t4];
                unsigned bl1 = BsL[n0 * 20 + ks + t4 + 4];
                float* c = acc[nt];
                mma_tf32(c[0], c[1], c[2], c[3], ah0, ah1, ah2, ah3, bl0, bl1);
                mma_tf32(c[0], c[1], c[2], c[3], al0, al1, al2, al3, bh0, bh1);
                mma_tf32(c[0], c[1], c[2], c[3], ah0, ah1, ah2, ah3, bh0, bh1);
            }
        }
        __syncthreads();
    }

#pragma unroll
    for (int nt = 0; nt < 4; nt++) {
        int col = colBase + wn + (nt << 3) + (t4 << 1);
        float bx = bias[col], by = bias[col + 1];
        int p = (col & 63) >> 1;
        float fr = g_freq[p];
        int row = rowBase + wm + g;
        float* c = acc[nt];
        float x0 = c[0] + bx, x1 = c[1] + by;
        float y0 = c[2] + bx, y1 = c[3] + by;
        if (rope) {
            float sv, cv;
            sincosf((float)(row & 1023) * fr, &sv, &cv);
            float t0 = x0 * cv - x1 * sv;
            x1 = x1 * cv + x0 * sv; x0 = t0;
            sincosf((float)((row + 8) & 1023) * fr, &sv, &cv);
            float u0 = y0 * cv - y1 * sv;
            y1 = y1 * cv + y0 * sv; y0 = u0;
        }
        *(float2*)&C[(size_t)row * 512 + col] = make_float2(x0, x1);
        *(float2*)&C[(size_t)(row + 8) * 512 + col] = make_float2(y0, y1);
    }
}

// merged projection GEMMs: z=0 q(+rope), z=1 k(+rope), z=2 v
__global__ __launch_bounds__(128) void proj_gemm_kernel(
    const float* __restrict__ q, const float* __restrict__ k,
    const float* __restrict__ v,
    const float* __restrict__ Wq, const float* __restrict__ bq,
    const float* __restrict__ Wv, const float* __restrict__ bv,
    float* __restrict__ qp, float* __restrict__ kp, float* __restrict__ vp) {
    const int z = blockIdx.z;
    const float* A = (z == 0) ? q : (z == 1) ? k : v;
    const float* W = (z == 2) ? Wv : Wq;
    const float* bias = (z == 2) ? bv : bq;
    float* C = (z == 0) ? qp : (z == 1) ? kp : vp;
    gemm_core(A, W, bias, C, z < 2, blockIdx.y << 5, blockIdx.x << 6);
}

__global__ __launch_bounds__(128) void gemm_bias_kernel(
    const float* __restrict__ A, const float* __restrict__ W,
    const float* __restrict__ bias, float* __restrict__ C) {
    gemm_core(A, W, bias, C, 0, blockIdx.y << 5, blockIdx.x << 6);
}

// ---------------- fused attention (R4 shape: 256 thr, 2 CTAs/SM) ----------------
// smem: Ssm[16][1028], QH/QL[16][68] (tf32 hi/lo), KV[128][68].
__global__ __launch_bounds__(256, 2) void attn_kernel(
    const float* __restrict__ qp, const float* __restrict__ kp,
    const float* __restrict__ vp, const float* __restrict__ gammas,
    float* __restrict__ attn_out, float* __restrict__ op) {
    extern __shared__ __align__(16) float sm[];
    float* Ssm = sm;                                   // 16*1028
    unsigned* QH = (unsigned*)(sm + 16 * SST);         // 16*68
    unsigned* QL = QH + 16 * 68;                       // 16*68
    float* KV = (float*)(QL + 16 * 68);                // 128*68

    const int tid = threadIdx.x;
    const int bh = blockIdx.y, b = bh >> 3, h = bh & 7;
    const int i0 = (int)(gridDim.x - 1 - blockIdx.x) << 4;  // big blocks first
    const int r4 = tid >> 6, c = tid & 63;
    const int jtMax = (i0 + 15) >> 7;
    const int warp = tid >> 5, lane = tid & 31;
    const int g = lane >> 2, t4 = lane & 3;

    // load+scale+split Q tile (one float4 per thread)
    {
        int r = tid >> 4, dq = (tid & 15) << 2;
        float4 v = *(const float4*)&qp[(size_t)((b << 10) + i0 + r) * 512 + (h << 6) + dq];
        split1(v.x * 0.125f, QH[r * 68 + dq + 0], QL[r * 68 + dq + 0]);
        split1(v.y * 0.125f, QH[r * 68 + dq + 1], QL[r * 68 + dq + 1]);
        split1(v.z * 0.125f, QH[r * 68 + dq + 2], QL[r * 68 + dq + 2]);
        split1(v.w * 0.125f, QH[r * 68 + dq + 3], QL[r * 68 + dq + 3]);
    }
    __syncthreads();

    // ---- scores = Q K^T via 3xTF32 mma; 128-wide j tiles, warp owns 16 cols ----
    for (int jt = 0; jt <= jtMax; jt++) {
        int j0 = jt << 7;
#pragma unroll
        for (int l = 0; l < 8; l++) {
            int e = tid + (l << 8);
            int j = e >> 4, dq = (e & 15) << 2;
            *(float4*)&KV[j * 68 + dq] =
                *(const float4*)&kp[(size_t)((b << 10) + j0 + j) * 512 + (h << 6) + dq];
        }
        __syncthreads();
        const int jn = (warp << 4);
        float acc[2][4] = {};
#pragma unroll
        for (int ks = 0; ks < 64; ks += 8) {
            unsigned ah0 = QH[g * 68 + ks + t4];
            unsigned ah1 = QH[(g + 8) * 68 + ks + t4];
            unsigned ah2 = QH[g * 68 + ks + t4 + 4];
            unsigned ah3 = QH[(g + 8) * 68 + ks + t4 + 4];
            unsigned al0 = QL[g * 68 + ks + t4];
            unsigned al1 = QL[(g + 8) * 68 + ks + t4];
            unsigned al2 = QL[g * 68 + ks + t4 + 4];
            unsigned al3 = QL[(g + 8) * 68 + ks + t4 + 4];
#pragma unroll
            for (int nt = 0; nt < 2; nt++) {
                int j = jn + (nt << 3) + g;
                float kb0 = KV[j * 68 + ks + t4];
                float kb1 = KV[j * 68 + ks + t4 + 4];
                unsigned bh0, bl0, bh1, bl1;
                split1(kb0, bh0, bl0);
                split1(kb1, bh1, bl1);
                float* cc = acc[nt];
                mma_tf32(cc[0], cc[1], cc[2], cc[3], ah0, ah1, ah2, ah3, bl0, bl1);
                mma_tf32(cc[0], cc[1], cc[2], cc[3], al0, al1, al2, al3, bh0, bh1);
                mma_tf32(cc[0], cc[1], cc[2], cc[3], ah0, ah1, ah2, ah3, bh0, bh1);
            }
        }
#pragma unroll
        for (int nt = 0; nt < 2; nt++) {
            int jc = j0 + jn + (nt << 3) + (t4 << 1);
            *(float2*)&Ssm[g * SST + jc] = make_float2(acc[nt][0], acc[nt][1]);
            *(float2*)&Ssm[(g + 8) * SST + jc] = make_float2(acc[nt][2], acc[nt][3]);
        }
        __syncthreads();
    }

    // ---- row phase: softmax1, cumsum, decay gate, ALiBi, softmax2, attn write ----
    const float gamma = gammas[h];
    const float gg = -(fmaxf(gamma, 0.0f) + log1pf(expf(-fabsf(gamma))));  // -softplus
    const float g2 = gg * gg;
    const float slope = exp2f(-(float)(h + 1));
    const int jpad = (jtMax + 1) << 7;

    for (int rr = 0; rr < 2; rr++) {
        int r = (warp << 1) + rr;
        int gi = i0 + r;
        int n = gi + 1;
        float* Srow = Ssm + r * SST;

        // max
        float mx = -3.0e38f;
        for (int j = lane; j < n; j += 32) mx = fmaxf(mx, Srow[j]);
#pragma unroll
        for (int o = 16; o; o >>= 1) mx = fmaxf(mx, __shfl_xor_sync(0xffffffffu, mx, o));
        // sum of exp
        float se = 0.0f;
        for (int j = lane; j < n; j += 32) se += __expf(Srow[j] - mx);
#pragma unroll
        for (int o = 16; o; o >>= 1) se += __shfl_xor_sync(0xffffffffu, se, o);
        float inv = 1.0f / se;
        // disttot = sum of rounded probabilities
        float dt = 0.0f;
        for (int j = lane; j < n; j += 32) dt += __expf(Srow[j] - mx) * inv;
#pragma unroll
        for (int o = 16; o; o >>= 1) dt += __shfl_xor_sync(0xffffffffu, dt, o);

        // cumsum scan + effect + alibi, track max2
        float carry = 0.0f, mx2 = -3.0e38f;
        for (int jb = 0; jb < n; jb += 32) {
            int j = jb + lane;
            float v = (j < n) ? __expf(Srow[j] - mx) * inv : 0.0f;
            float x = v;
#pragma unroll
            for (int o = 1; o < 32; o <<= 1) {
                float y = __shfl_up_sync(0xffffffffu, x, o);
                if (lane >= o) x += y;
            }
            if (j < n) {
                float cum = x + carry;
                float suf = dt - cum;
                float pos = (float)(gi - j);
                float d2 = fmaxf(suf, 0.0f) * pos;
                float eff;
                if (g2 * d2 > 132.6f) {
                    eff = 1e-5f;
                } else {
                    eff = fmaxf(__expf(gg * sqrtf(d2)), 1e-5f);
                }
                float s2 = Srow[j] * eff + slope * (float)j;
                Srow[j] = s2;
                mx2 = fmaxf(mx2, s2);
            }
            carry += __shfl_sync(0xffffffffu, x, 31);
        }
#pragma unroll
        for (int o = 16; o; o >>= 1) mx2 = fmaxf(mx2, __shfl_xor_sync(0xffffffffu, mx2, o));

        // softmax2 sum (store exp in place)
        float se2 = 0.0f;
        for (int j = lane; j < n; j += 32) {
            float dlt = Srow[j] - mx2;
            float e2 = (dlt > -87.3f) ? __expf(dlt) : 0.0f;
            Srow[j] = e2;
            se2 += e2;
        }
#pragma unroll
        for (int o = 16; o; o >>= 1) se2 += __shfl_xor_sync(0xffffffffu, se2, o);
        float inv2 = 1.0f / se2;

        float* arow = attn_out + ((size_t)bh << 20) + ((size_t)gi << 10);
        for (int j = lane; j < 1024; j += 32) {
            float a = (j < n) ? Srow[j] * inv2 : 0.0f;
            arow[j] = a;
            if (j < jpad) Srow[j] = a;
        }
    }
    __syncthreads();

    // ---- out = attn @ V (SIMT fp32) ----
    float o0 = 0, o1 = 0, o2 = 0, o3 = 0;
    for (int jt = 0; jt <= jtMax; jt++) {
        int j0 = jt << 7;
#pragma unroll
        for (int l = 0; l < 8; l++) {
            int e = tid + (l << 8);
            int j = e >> 4, dq = (e & 15) << 2;
            *(float4*)&KV[j * 68 + dq] =
                *(const float4*)&vp[(size_t)((b << 10) + j0 + j) * 512 + (h << 6) + dq];
        }
        __syncthreads();
#pragma unroll 8
        for (int jq = 0; jq < 128; jq += 4) {
            float4 s0 = *(const float4*)&Ssm[r4 * SST + j0 + jq];
            float4 s1 = *(const float4*)&Ssm[(r4 + 4) * SST + j0 + jq];
            float4 s2 = *(const float4*)&Ssm[(r4 + 8) * SST + j0 + jq];
            float4 s3 = *(const float4*)&Ssm[(r4 + 12) * SST + j0 + jq];
            float v0 = KV[(jq + 0) * 68 + c];
            float v1 = KV[(jq + 1) * 68 + c];
            float v2 = KV[(jq + 2) * 68 + c];
            float v3 = KV[(jq + 3) * 68 + c];
            o0 += s0.x * v0 + s0.y * v1 + s0.z * v2 + s0.w * v3;
            o1 += s1.x * v0 + s1.y * v1 + s1.z * v2 + s1.w * v3;
            o2 += s2.x * v0 + s2.y * v1 + s2.z * v2 + s2.w * v3;
            o3 += s3.x * v0 + s3.y * v1 + s3.z * v2 + s3.w * v3;
        }
        __syncthreads();
    }
    op[(size_t)((b << 10) + i0 + r4) * 512 + (h << 6) + c] = o0;
    op[(size_t)((b << 10) + i0 + r4 + 4) * 512 + (h << 6) + c] = o1;
    op[(size_t)((b << 10) + i0 + r4 + 8) * 512 + (h << 6) + c] = o2;
    op[(size_t)((b << 10) + i0 + r4 + 12) * 512 + (h << 6) + c] = o3;
}

// ---------------- launch ----------------
extern "C" void kernel_launch(void* const* d_in, const int* in_sizes, int n_in,
                              void* d_out, int out_size) {
    const float* q      = (const float*)d_in[0];
    const float* k      = (const float*)d_in[1];
    const float* v      = (const float*)d_in[2];
    // d_in[3] = mask (tril causal) — structure used implicitly
    const float* Wq     = (const float*)d_in[4];
    const float* bq     = (const float*)d_in[5];
    const float* Wv     = (const float*)d_in[6];
    const float* bv     = (const float*)d_in[7];
    const float* Wo     = (const float*)d_in[8];
    const float* bo     = (const float*)d_in[9];
    const float* gammas = (const float*)d_in[10];

    float* out  = (float*)d_out;                       // [B,S,D]
    float* attn = out + (size_t)Mrows * Dd;            // [B,H,S,S]

    float *qp, *kp, *vp, *op;
    cudaGetSymbolAddress((void**)&qp, g_qp);
    cudaGetSymbolAddress((void**)&kp, g_kp);
    cudaGetSymbolAddress((void**)&vp, g_vp);
    cudaGetSymbolAddress((void**)&op, g_op);

    const int ATTN_SMEM = (16 * SST + 16 * 68 * 2 + 128 * 68) * 4;  // 109312 B
    cudaFuncSetAttribute(attn_kernel, cudaFuncAttributeMaxDynamicSharedMemorySize,
                         ATTN_SMEM);

    freq_init_kernel<<<1, 32>>>();

    proj_gemm_kernel<<<dim3(8, 128, 3), 128>>>(q, k, v, Wq, bq, Wv, bv, qp, kp, vp);

    attn_kernel<<<dim3(64, 32), 256, ATTN_SMEM>>>(qp, kp, vp, gammas, attn, op);

    gemm_bias_kernel<<<dim3(8, 128), 128>>>(op, Wo, bo, out);
}